// round 3
// baseline (speedup 1.0000x reference)
#include <cuda_runtime.h>
#include <math.h>

#define BB     1024
#define HH     256
#define FOURH  1024
#define LAT    128
#define ROWS   8
#define NCTA   (BB / ROWS)      // 128 CTAs
#define NT     256              // threads per CTA, thread t owns H-column j=t
#define GSIZE  64               // group size for GroupNorm (256/4)
#define EPSG   1e-5f

// -------- device scratch (allocation-free rule: __device__ globals) --------
// Gate-interleaved, k-major transposed weights: element [k][j] is a float4
// holding W[(g*H+j), k] for g = i,f,g,o.
__device__ float4 g_Wt0 [HH * HH];   // Whh0^T
__device__ float4 g_Wt1i[HH * HH];   // Wih1^T
__device__ float4 g_Wt1h[HH * HH];   // Whh1^T
__device__ float  g_Wut [LAT * HH];  // W_unpack^T  [k][j]

__device__ __forceinline__ float tanh_fast(float x) {
    float y;
    asm("tanh.approx.f32 %0, %1;" : "=f"(y) : "f"(x));
    return y;
}
__device__ __forceinline__ float sig_fast(float x) {
    return 0.5f * tanh_fast(0.5f * x) + 0.5f;
}

// -------- prologue: transpose weights into k-major gate-interleaved layout ----
__global__ void prep_kernel(const float* __restrict__ Whh0,
                            const float* __restrict__ Wih1,
                            const float* __restrict__ Whh1,
                            const float* __restrict__ Wu) {
    int i = blockIdx.x * blockDim.x + threadIdx.x;
    if (i < HH * FOURH) {
        int k   = i >> 10;          // / 1024
        int rem = i & 1023;
        int j   = rem >> 2;
        int g   = rem & 3;
        int src = (g * HH + j) * HH + k;   // row n = g*256+j, col k of (1024,256)
        ((float*)g_Wt0)[i]  = Whh0[src];
        ((float*)g_Wt1i)[i] = Wih1[src];
        ((float*)g_Wt1h)[i] = Whh1[src];
    }
    if (i < LAT * HH) {
        int k = i >> 8, j = i & 255;       // W_unpack is (256,128)
        g_Wut[i] = Wu[j * LAT + k];
    }
}

// -------- main persistent kernel: 8 batch rows per CTA, full recurrence ------
__global__ __launch_bounds__(NT, 1)
void gen_kernel(const float* __restrict__ noise,
                const float* __restrict__ b_unpack,
                const float* __restrict__ Wih0,
                const float* __restrict__ bih0, const float* __restrict__ bhh0,
                const float* __restrict__ bih1, const float* __restrict__ bhh1,
                const float* __restrict__ gamma_a, const float* __restrict__ beta_a,
                const float* __restrict__ Wa, const float* __restrict__ ba,
                const float* __restrict__ gamma_w, const float* __restrict__ beta_w,
                const float* __restrict__ Ww, const float* __restrict__ bw,
                int T, float* __restrict__ out) {
    __shared__ __align__(16) float sh0[ROWS][HH];
    __shared__ __align__(16) float sh1[ROWS][HH];
    __shared__ float snoise[ROWS][LAT];
    __shared__ float sGA[HH], sBA[HH], sGW[HH], sBW[HH];
    __shared__ float sStat[ROWS][4][2];     // [row][group][mu, rstd]
    __shared__ float scoord[ROWS][2];

    const int t    = threadIdx.x;           // H-column this thread owns
    const int r0   = blockIdx.x * ROWS;
    const int warp = t >> 5;
    const int lane = t & 31;

    // Head constants folded: contribution of column j is (xn*gamma+beta)*W
    {
        float wav = Wa[t], wwv = Ww[t];
        sGA[t] = gamma_a[t] * wav;  sBA[t] = beta_a[t] * wav;
        sGW[t] = gamma_w[t] * wwv;  sBW[t] = beta_w[t] * wwv;
    }
    const float bav = ba[0], bwv = bw[0];

    // Per-thread gate constants (4 gates for column t)
    float bias0[4], bias1[4], wi0a[4], wi0b[4];
#pragma unroll
    for (int g = 0; g < 4; g++) {
        int n = g * HH + t;
        bias0[g] = bih0[n] + bhh0[n];
        bias1[g] = bih1[n] + bhh1[n];
        wi0a[g]  = Wih0[n * 2 + 0];
        wi0b[g]  = Wih0[n * 2 + 1];
    }

    // Stage noise rows
    for (int i = t; i < ROWS * LAT; i += NT)
        ((float*)snoise)[i] = noise[(size_t)r0 * LAT + i];
    if (t < ROWS * 2) ((float*)scoord)[t] = 0.f;
    __syncthreads();

    // idea = elu(noise @ W_unpack^T + b_unpack); h0=c0=idea, h1=c1=0
    float c0r[ROWS], c1r[ROWS];
    {
        float acc[ROWS];
        float bu = b_unpack[t];
#pragma unroll
        for (int r = 0; r < ROWS; r++) acc[r] = bu;
        for (int k = 0; k < LAT; k++) {
            float w = g_Wut[k * HH + t];
#pragma unroll
            for (int r = 0; r < ROWS; r++) acc[r] = fmaf(snoise[r][k], w, acc[r]);
        }
#pragma unroll
        for (int r = 0; r < ROWS; r++) {
            float v = acc[r];
            float e = (v > 0.f) ? v : (expf(v) - 1.f);
            sh0[r][t] = e;  c0r[r] = e;
            sh1[r][t] = 0.f; c1r[r] = 0.f;
        }
    }
    __syncthreads();

    const float4* __restrict__ w0  = g_Wt0  + t;
    const float4* __restrict__ w1i = g_Wt1i + t;
    const float4* __restrict__ w1h = g_Wt1h + t;

    for (int step = 0; step < T; ++step) {
        // ======== layer 0: gates = h0 @ Whh0^T + coords @ Wih0^T + bias ========
        float acc[4][ROWS];
#pragma unroll
        for (int g = 0; g < 4; g++)
#pragma unroll
            for (int r = 0; r < ROWS; r++)
                acc[g][r] = fmaf(wi0a[g], scoord[r][0],
                           fmaf(wi0b[g], scoord[r][1], bias0[g]));
#pragma unroll 4
        for (int k = 0; k < HH; k++) {
            float4 w = __ldg(&w0[k * HH]);
#pragma unroll
            for (int r = 0; r < ROWS; r++) {
                float hv = sh0[r][k];
                acc[0][r] = fmaf(w.x, hv, acc[0][r]);
                acc[1][r] = fmaf(w.y, hv, acc[1][r]);
                acc[2][r] = fmaf(w.z, hv, acc[2][r]);
                acc[3][r] = fmaf(w.w, hv, acc[3][r]);
            }
        }
        float h0new[ROWS];
#pragma unroll
        for (int r = 0; r < ROWS; r++) {
            float ig = sig_fast(acc[0][r]);
            float fg = sig_fast(acc[1][r]);
            float gg = tanh_fast(acc[2][r]);
            float og = sig_fast(acc[3][r]);
            float cn = fmaf(fg, c0r[r], ig * gg);
            c0r[r]   = cn;
            h0new[r] = og * tanh_fast(cn);
        }
        __syncthreads();                       // everyone done reading old sh0
#pragma unroll
        for (int r = 0; r < ROWS; r++) sh0[r][t] = h0new[r];
        __syncthreads();

        // ======== layer 1: gates = h0_new @ Wih1^T + h1 @ Whh1^T + bias ========
#pragma unroll
        for (int g = 0; g < 4; g++)
#pragma unroll
            for (int r = 0; r < ROWS; r++) acc[g][r] = bias1[g];
#pragma unroll 2
        for (int k = 0; k < HH; k++) {
            float4 wi = __ldg(&w1i[k * HH]);
            float4 wh = __ldg(&w1h[k * HH]);
#pragma unroll
            for (int r = 0; r < ROWS; r++) {
                float a = sh0[r][k];
                float b = sh1[r][k];
                acc[0][r] = fmaf(wi.x, a, fmaf(wh.x, b, acc[0][r]));
                acc[1][r] = fmaf(wi.y, a, fmaf(wh.y, b, acc[1][r]));
                acc[2][r] = fmaf(wi.z, a, fmaf(wh.z, b, acc[2][r]));
                acc[3][r] = fmaf(wi.w, a, fmaf(wh.w, b, acc[3][r]));
            }
        }
        float h1new[ROWS];
#pragma unroll
        for (int r = 0; r < ROWS; r++) {
            float ig = sig_fast(acc[0][r]);
            float fg = sig_fast(acc[1][r]);
            float gg = tanh_fast(acc[2][r]);
            float og = sig_fast(acc[3][r]);
            float cn = fmaf(fg, c1r[r], ig * gg);
            c1r[r]   = cn;
            h1new[r] = og * tanh_fast(cn);
        }
        __syncthreads();                       // everyone done reading old sh1
#pragma unroll
        for (int r = 0; r < ROWS; r++) sh1[r][t] = h1new[r];
        __syncthreads();

        // ======== GroupNorm stats: warp w handles row w ========
        {
            int r = warp;
#pragma unroll
            for (int g = 0; g < 4; g++) {
                float v0 = sh1[r][g * GSIZE + lane];
                float v1 = sh1[r][g * GSIZE + 32 + lane];
                float s = v0 + v1, q = fmaf(v0, v0, v1 * v1);
#pragma unroll
                for (int off = 16; off; off >>= 1) {
                    s += __shfl_xor_sync(0xffffffffu, s, off);
                    q += __shfl_xor_sync(0xffffffffu, q, off);
                }
                if (lane == 0) {
                    float mu  = s * (1.f / GSIZE);
                    float var = q * (1.f / GSIZE) - mu * mu;
                    sStat[r][g][0] = mu;
                    sStat[r][g][1] = rsqrtf(var + EPSG);
                }
            }
        }
        __syncthreads();

        // ======== heads: angle = tanh(gn_a(h1)@Wa+ba), width = sig(gn_w(h1)@Ww+bw)
        {
            int r = warp;
            float aacc = 0.f, wacc = 0.f;
#pragma unroll
            for (int jj = 0; jj < HH; jj += 32) {
                int j = jj + lane;
                int g = jj >> 6;               // uniform per iteration
                float xn = (sh1[r][j] - sStat[r][g][0]) * sStat[r][g][1];
                aacc += fmaf(xn, sGA[j], sBA[j]);
                wacc += fmaf(xn, sGW[j], sBW[j]);
            }
#pragma unroll
            for (int off = 16; off; off >>= 1) {
                aacc += __shfl_xor_sync(0xffffffffu, aacc, off);
                wacc += __shfl_xor_sync(0xffffffffu, wacc, off);
            }
            if (lane == 0) {
                float ang = tanh_fast(aacc + bav);
                float wid = sig_fast(wacc + bwv);
                scoord[r][0] = ang;
                scoord[r][1] = wid;
                float2* op = (float2*)(out + ((size_t)(r0 + r) * T + step) * 2);
                *op = make_float2(ang, wid);
            }
        }
        __syncthreads();                       // coords visible for next step
    }
}

extern "C" void kernel_launch(void* const* d_in, const int* in_sizes, int n_in,
                              void* d_out, int out_size) {
    const float* noise    = (const float*)d_in[0];
    const float* W_unpack = (const float*)d_in[1];
    const float* b_unpack = (const float*)d_in[2];
    const float* Wih0     = (const float*)d_in[3];
    const float* Whh0     = (const float*)d_in[4];
    const float* bih0     = (const float*)d_in[5];
    const float* bhh0     = (const float*)d_in[6];
    const float* Wih1     = (const float*)d_in[7];
    const float* Whh1     = (const float*)d_in[8];
    const float* bih1     = (const float*)d_in[9];
    const float* bhh1     = (const float*)d_in[10];
    const float* gamma_a  = (const float*)d_in[11];
    const float* beta_a   = (const float*)d_in[12];
    const float* Wa       = (const float*)d_in[13];
    const float* ba       = (const float*)d_in[14];
    const float* gamma_w  = (const float*)d_in[15];
    const float* beta_w   = (const float*)d_in[16];
    const float* Ww       = (const float*)d_in[17];
    const float* bw       = (const float*)d_in[18];
    (void)in_sizes; (void)n_in;

    // T derived host-side from output size: out is (B, T, 2) float32
    int T = out_size / (BB * 2);

    prep_kernel<<<(HH * FOURH + 255) / 256, 256>>>(Whh0, Wih1, Whh1, W_unpack);
    gen_kernel<<<NCTA, NT>>>(noise, b_unpack, Wih0, bih0, bhh0, bih1, bhh1,
                             gamma_a, beta_a, Wa, ba, gamma_w, beta_w, Ww, bw,
                             T, (float*)d_out);
}

// round 4
// speedup vs baseline: 1.0761x; 1.0761x over previous
#include <cuda_runtime.h>
#include <math.h>

#define BB     1024
#define HH     256
#define FOURH  1024
#define LAT    128
#define ROWS   8
#define NCTA   (BB / ROWS)      // 128 CTAs
#define NT     256              // thread t owns H-column j=t
#define GSIZE  64
#define EPSG   1e-5f

typedef unsigned long long u64;

// -------- device scratch --------
// Gate-interleaved, k-major transposed weights: [k][j] float4 = W[(g*H+j),k], g=i,f,g,o
__device__ float4 g_Wt0 [HH * HH];   // Whh0^T
__device__ float4 g_Wt1i[HH * HH];   // Wih1^T
__device__ float4 g_Wt1h[HH * HH];   // Whh1^T
__device__ float  g_Wut [LAT * HH];  // W_unpack^T [k][j]

__device__ __forceinline__ float tanh_fast(float x) {
    float y; asm("tanh.approx.f32 %0, %1;" : "=f"(y) : "f"(x)); return y;
}
__device__ __forceinline__ float sig_fast(float x) {
    return 0.5f * tanh_fast(0.5f * x) + 0.5f;
}
__device__ __forceinline__ u64 pack2(float lo, float hi) {
    u64 r; asm("mov.b64 %0, {%1, %2};" : "=l"(r) : "f"(lo), "f"(hi)); return r;
}
__device__ __forceinline__ void unpack2(u64 v, float& lo, float& hi) {
    asm("mov.b64 {%0, %1}, %2;" : "=f"(lo), "=f"(hi) : "l"(v));
}
__device__ __forceinline__ u64 fma2(u64 a, u64 b, u64 c) {
    u64 d; asm("fma.rn.f32x2 %0, %1, %2, %3;" : "=l"(d) : "l"(a), "l"(b), "l"(c)); return d;
}
__device__ __forceinline__ void ldg_v2u64(const void* p, u64& a, u64& b) {
    asm("ld.global.nc.v2.u64 {%0, %1}, [%2];" : "=l"(a), "=l"(b) : "l"(p));
}

// -------- prologue: transpose weights --------
__global__ void prep_kernel(const float* __restrict__ Whh0,
                            const float* __restrict__ Wih1,
                            const float* __restrict__ Whh1,
                            const float* __restrict__ Wu) {
    int i = blockIdx.x * blockDim.x + threadIdx.x;
    if (i < HH * FOURH) {
        int k   = i >> 10;
        int rem = i & 1023;
        int j   = rem >> 2;
        int g   = rem & 3;
        int src = (g * HH + j) * HH + k;
        ((float*)g_Wt0)[i]  = Whh0[src];
        ((float*)g_Wt1i)[i] = Wih1[src];
        ((float*)g_Wt1h)[i] = Whh1[src];
    }
    if (i < LAT * HH) {
        int k = i >> 8, j = i & 255;
        g_Wut[i] = Wu[j * LAT + k];
    }
}

// -------- main persistent kernel --------
__global__ __launch_bounds__(NT, 1)
void gen_kernel(const float* __restrict__ noise,
                const float* __restrict__ b_unpack,
                const float* __restrict__ Wih0,
                const float* __restrict__ bih0, const float* __restrict__ bhh0,
                const float* __restrict__ bih1, const float* __restrict__ bhh1,
                const float* __restrict__ gamma_a, const float* __restrict__ beta_a,
                const float* __restrict__ Wa, const float* __restrict__ ba,
                const float* __restrict__ gamma_w, const float* __restrict__ beta_w,
                const float* __restrict__ Ww, const float* __restrict__ bw,
                int T, float* __restrict__ out) {
    // h duplicated per element as (h,h) u64: [k][r], 16B-aligned rows of 8
    __shared__ __align__(16) u64 sh0d[HH][ROWS];   // 16KB
    __shared__ __align__(16) u64 sh1d[HH][ROWS];   // 16KB
    __shared__ float sh1n[ROWS][HH];               // 8KB, linear copy for GN/heads
    __shared__ float sGA[HH], sBA[HH], sGW[HH], sBW[HH];
    __shared__ float sStat[ROWS][4][2];
    __shared__ float scoord[ROWS][2];

    const int t    = threadIdx.x;
    const int r0   = blockIdx.x * ROWS;
    const int warp = t >> 5;
    const int lane = t & 31;

    {
        float wav = Wa[t], wwv = Ww[t];
        sGA[t] = gamma_a[t] * wav;  sBA[t] = beta_a[t] * wav;
        sGW[t] = gamma_w[t] * wwv;  sBW[t] = beta_w[t] * wwv;
    }
    const float bav = ba[0], bwv = bw[0];

    // Per-thread packed gate constants (gate pairs 01=(i,f), 23=(g,o))
    u64 bias0_01, bias0_23, bias1_01, bias1_23;
    u64 wi0a_01, wi0a_23, wi0b_01, wi0b_23;
    {
        float b0[4], b1[4], wa[4], wb[4];
#pragma unroll
        for (int g = 0; g < 4; g++) {
            int n = g * HH + t;
            b0[g] = bih0[n] + bhh0[n];
            b1[g] = bih1[n] + bhh1[n];
            wa[g] = Wih0[n * 2 + 0];
            wb[g] = Wih0[n * 2 + 1];
        }
        bias0_01 = pack2(b0[0], b0[1]); bias0_23 = pack2(b0[2], b0[3]);
        bias1_01 = pack2(b1[0], b1[1]); bias1_23 = pack2(b1[2], b1[3]);
        wi0a_01  = pack2(wa[0], wa[1]); wi0a_23  = pack2(wa[2], wa[3]);
        wi0b_01  = pack2(wb[0], wb[1]); wi0b_23  = pack2(wb[2], wb[3]);
    }

    // Stage noise (alias sh1d as scratch; sh1d re-initialized after)
    float* snoise = (float*)sh1d;
    for (int i = t; i < ROWS * LAT; i += NT)
        snoise[i] = noise[(size_t)r0 * LAT + i];
    if (t < ROWS * 2) ((float*)scoord)[t] = 0.f;
    __syncthreads();

    // idea = elu(noise @ W_unpack^T + b_unpack)
    float c0r[ROWS], c1r[ROWS];
    {
        float acc[ROWS];
        float bu = b_unpack[t];
#pragma unroll
        for (int r = 0; r < ROWS; r++) acc[r] = bu;
        for (int k = 0; k < LAT; k++) {
            float w = g_Wut[k * HH + t];
#pragma unroll
            for (int r = 0; r < ROWS; r++) acc[r] = fmaf(snoise[r * LAT + k], w, acc[r]);
        }
        __syncthreads();   // done reading snoise before overwriting sh1d
#pragma unroll
        for (int r = 0; r < ROWS; r++) {
            float v = acc[r];
            float e = (v > 0.f) ? v : (expf(v) - 1.f);
            sh0d[t][r] = pack2(e, e);
            c0r[r] = e;
            sh1d[t][r] = 0ull;
            sh1n[r][t] = 0.f;
            c1r[r] = 0.f;
        }
    }
    __syncthreads();

    const float4* __restrict__ w0  = g_Wt0  + t;
    const float4* __restrict__ w1i = g_Wt1i + t;
    const float4* __restrict__ w1h = g_Wt1h + t;

    for (int step = 0; step < T; ++step) {
        // ================= layer 0 =================
        u64 a01[ROWS], a23[ROWS];
#pragma unroll
        for (int r = 0; r < ROWS; r++) {
            u64 cx = pack2(scoord[r][0], scoord[r][0]);
            u64 cy = pack2(scoord[r][1], scoord[r][1]);
            a01[r] = fma2(wi0a_01, cx, fma2(wi0b_01, cy, bias0_01));
            a23[r] = fma2(wi0a_23, cx, fma2(wi0b_23, cy, bias0_23));
        }
#pragma unroll 4
        for (int k = 0; k < HH; k++) {
            u64 w01, w23;
            ldg_v2u64(&w0[k * HH], w01, w23);
            ulonglong2 h0 = *(const ulonglong2*)&sh0d[k][0];
            ulonglong2 h1 = *(const ulonglong2*)&sh0d[k][2];
            ulonglong2 h2 = *(const ulonglong2*)&sh0d[k][4];
            ulonglong2 h3 = *(const ulonglong2*)&sh0d[k][6];
            u64 h[ROWS] = {h0.x, h0.y, h1.x, h1.y, h2.x, h2.y, h3.x, h3.y};
#pragma unroll
            for (int r = 0; r < ROWS; r++) {
                a01[r] = fma2(w01, h[r], a01[r]);
                a23[r] = fma2(w23, h[r], a23[r]);
            }
        }
        float h0new[ROWS];
#pragma unroll
        for (int r = 0; r < ROWS; r++) {
            float gi, gf, gg, go;
            unpack2(a01[r], gi, gf);
            unpack2(a23[r], gg, go);
            float cn = fmaf(sig_fast(gf), c0r[r], sig_fast(gi) * tanh_fast(gg));
            c0r[r]   = cn;
            h0new[r] = sig_fast(go) * tanh_fast(cn);
        }
        __syncthreads();
#pragma unroll
        for (int r = 0; r < ROWS; r++) sh0d[t][r] = pack2(h0new[r], h0new[r]);
        __syncthreads();

        // ================= layer 1 =================
#pragma unroll
        for (int r = 0; r < ROWS; r++) { a01[r] = bias1_01; a23[r] = bias1_23; }
#pragma unroll 2
        for (int k = 0; k < HH; k++) {
            u64 wi01, wi23, wh01, wh23;
            ldg_v2u64(&w1i[k * HH], wi01, wi23);
            ldg_v2u64(&w1h[k * HH], wh01, wh23);
            ulonglong2 p0 = *(const ulonglong2*)&sh0d[k][0];
            ulonglong2 p1 = *(const ulonglong2*)&sh0d[k][2];
            ulonglong2 p2 = *(const ulonglong2*)&sh0d[k][4];
            ulonglong2 p3 = *(const ulonglong2*)&sh0d[k][6];
            ulonglong2 q0 = *(const ulonglong2*)&sh1d[k][0];
            ulonglong2 q1 = *(const ulonglong2*)&sh1d[k][2];
            ulonglong2 q2 = *(const ulonglong2*)&sh1d[k][4];
            ulonglong2 q3 = *(const ulonglong2*)&sh1d[k][6];
            u64 ha[ROWS] = {p0.x, p0.y, p1.x, p1.y, p2.x, p2.y, p3.x, p3.y};
            u64 hb[ROWS] = {q0.x, q0.y, q1.x, q1.y, q2.x, q2.y, q3.x, q3.y};
#pragma unroll
            for (int r = 0; r < ROWS; r++) {
                a01[r] = fma2(wi01, ha[r], fma2(wh01, hb[r], a01[r]));
                a23[r] = fma2(wi23, ha[r], fma2(wh23, hb[r], a23[r]));
            }
        }
        float h1new[ROWS];
#pragma unroll
        for (int r = 0; r < ROWS; r++) {
            float gi, gf, gg, go;
            unpack2(a01[r], gi, gf);
            unpack2(a23[r], gg, go);
            float cn = fmaf(sig_fast(gf), c1r[r], sig_fast(gi) * tanh_fast(gg));
            c1r[r]   = cn;
            h1new[r] = sig_fast(go) * tanh_fast(cn);
        }
        __syncthreads();
#pragma unroll
        for (int r = 0; r < ROWS; r++) {
            sh1d[t][r] = pack2(h1new[r], h1new[r]);
            sh1n[r][t] = h1new[r];
        }
        __syncthreads();

        // ================= GroupNorm stats (warp w -> row w) =================
        {
            int r = warp;
#pragma unroll
            for (int g = 0; g < 4; g++) {
                float v0 = sh1n[r][g * GSIZE + lane];
                float v1 = sh1n[r][g * GSIZE + 32 + lane];
                float s = v0 + v1, q = fmaf(v0, v0, v1 * v1);
#pragma unroll
                for (int off = 16; off; off >>= 1) {
                    s += __shfl_xor_sync(0xffffffffu, s, off);
                    q += __shfl_xor_sync(0xffffffffu, q, off);
                }
                if (lane == 0) {
                    float mu  = s * (1.f / GSIZE);
                    float var = q * (1.f / GSIZE) - mu * mu;
                    sStat[r][g][0] = mu;
                    sStat[r][g][1] = rsqrtf(var + EPSG);
                }
            }
        }
        __syncthreads();

        // ================= heads =================
        {
            int r = warp;
            float aacc = 0.f, wacc = 0.f;
#pragma unroll
            for (int jj = 0; jj < HH; jj += 32) {
                int j = jj + lane;
                int g = jj >> 6;
                float xn = (sh1n[r][j] - sStat[r][g][0]) * sStat[r][g][1];
                aacc += fmaf(xn, sGA[j], sBA[j]);
                wacc += fmaf(xn, sGW[j], sBW[j]);
            }
#pragma unroll
            for (int off = 16; off; off >>= 1) {
                aacc += __shfl_xor_sync(0xffffffffu, aacc, off);
                wacc += __shfl_xor_sync(0xffffffffu, wacc, off);
            }
            if (lane == 0) {
                float ang = tanh_fast(aacc + bav);
                float wid = sig_fast(wacc + bwv);
                scoord[r][0] = ang;
                scoord[r][1] = wid;
                float2* op = (float2*)(out + ((size_t)(r0 + r) * T + step) * 2);
                *op = make_float2(ang, wid);
            }
        }
        __syncthreads();
    }
}

extern "C" void kernel_launch(void* const* d_in, const int* in_sizes, int n_in,
                              void* d_out, int out_size) {
    const float* noise    = (const float*)d_in[0];
    const float* W_unpack = (const float*)d_in[1];
    const float* b_unpack = (const float*)d_in[2];
    const float* Wih0     = (const float*)d_in[3];
    const float* Whh0     = (const float*)d_in[4];
    const float* bih0     = (const float*)d_in[5];
    const float* bhh0     = (const float*)d_in[6];
    const float* Wih1     = (const float*)d_in[7];
    const float* Whh1     = (const float*)d_in[8];
    const float* bih1     = (const float*)d_in[9];
    const float* bhh1     = (const float*)d_in[10];
    const float* gamma_a  = (const float*)d_in[11];
    const float* beta_a   = (const float*)d_in[12];
    const float* Wa       = (const float*)d_in[13];
    const float* ba       = (const float*)d_in[14];
    const float* gamma_w  = (const float*)d_in[15];
    const float* beta_w   = (const float*)d_in[16];
    const float* Ww       = (const float*)d_in[17];
    const float* bw       = (const float*)d_in[18];
    (void)in_sizes; (void)n_in;

    int T = out_size / (BB * 2);

    prep_kernel<<<(HH * FOURH + 255) / 256, 256>>>(Whh0, Wih1, Whh1, W_unpack);
    gen_kernel<<<NCTA, NT>>>(noise, b_unpack, Wih0, bih0, bhh0, bih1, bhh1,
                             gamma_a, beta_a, Wa, ba, gamma_w, beta_w, Ww, bw,
                             T, (float*)d_out);
}

// round 5
// speedup vs baseline: 1.5308x; 1.4226x over previous
#include <cuda_runtime.h>
#include <math.h>

#define BB     1024
#define HH     256
#define FOURH  1024
#define LAT    128
#define ROWS   8
#define NCTA   (BB / ROWS)      // 128 CTAs
#define NT     512              // (j, s): j = t & 255 owns H-column, s = t >> 8 owns k-half
#define KHALF  128
#define GSIZE  64
#define EPSG   1e-5f

typedef unsigned long long u64;

// -------- device scratch --------
// Gate-interleaved, k-major transposed weights: [k][j] float4 = W[(g*H+j),k], g=i,f,g,o
__device__ float4 g_Wt0 [HH * HH];   // Whh0^T
__device__ float4 g_Wt1i[HH * HH];   // Wih1^T
__device__ float4 g_Wt1h[HH * HH];   // Whh1^T
__device__ float  g_Wut [LAT * HH];  // W_unpack^T [k][j]

__device__ __forceinline__ float tanh_fast(float x) {
    float y; asm("tanh.approx.f32 %0, %1;" : "=f"(y) : "f"(x)); return y;
}
__device__ __forceinline__ float sig_fast(float x) {
    return 0.5f * tanh_fast(0.5f * x) + 0.5f;
}
__device__ __forceinline__ u64 pack2(float lo, float hi) {
    u64 r; asm("mov.b64 %0, {%1, %2};" : "=l"(r) : "f"(lo), "f"(hi)); return r;
}
__device__ __forceinline__ void unpack2(u64 v, float& lo, float& hi) {
    asm("mov.b64 {%0, %1}, %2;" : "=f"(lo), "=f"(hi) : "l"(v));
}
__device__ __forceinline__ u64 fma2(u64 a, u64 b, u64 c) {
    u64 d; asm("fma.rn.f32x2 %0, %1, %2, %3;" : "=l"(d) : "l"(a), "l"(b), "l"(c)); return d;
}
__device__ __forceinline__ u64 add2(u64 a, u64 b) {
    u64 d; asm("add.rn.f32x2 %0, %1, %2;" : "=l"(d) : "l"(a), "l"(b)); return d;
}
__device__ __forceinline__ void ldg_v2u64(const void* p, u64& a, u64& b) {
    asm("ld.global.nc.v2.u64 {%0, %1}, [%2];" : "=l"(a), "=l"(b) : "l"(p));
}

// -------- prologue: transpose weights --------
__global__ void prep_kernel(const float* __restrict__ Whh0,
                            const float* __restrict__ Wih1,
                            const float* __restrict__ Whh1,
                            const float* __restrict__ Wu) {
    int i = blockIdx.x * blockDim.x + threadIdx.x;
    if (i < HH * FOURH) {
        int k   = i >> 10;
        int rem = i & 1023;
        int j   = rem >> 2;
        int g   = rem & 3;
        int src = (g * HH + j) * HH + k;
        ((float*)g_Wt0)[i]  = Whh0[src];
        ((float*)g_Wt1i)[i] = Wih1[src];
        ((float*)g_Wt1h)[i] = Whh1[src];
    }
    if (i < LAT * HH) {
        int k = i >> 8, j = i & 255;
        g_Wut[i] = Wu[j * LAT + k];
    }
}

// -------- main persistent kernel --------
__global__ __launch_bounds__(NT, 1)
void gen_kernel(const float* __restrict__ noise,
                const float* __restrict__ b_unpack,
                const float* __restrict__ Wih0,
                const float* __restrict__ bih0, const float* __restrict__ bhh0,
                const float* __restrict__ bih1, const float* __restrict__ bhh1,
                const float* __restrict__ gamma_a, const float* __restrict__ beta_a,
                const float* __restrict__ Wa, const float* __restrict__ ba,
                const float* __restrict__ gamma_w, const float* __restrict__ beta_w,
                const float* __restrict__ Ww, const float* __restrict__ bw,
                int T, float* __restrict__ out) {
    // h duplicated per element as (h,h) u64: [k][r]
    __shared__ __align__(16) u64 sh0d[HH][ROWS];   // 16KB
    __shared__ __align__(16) u64 sh1d[HH][ROWS];   // 16KB
    __shared__ __align__(16) u64 red[HH][17];      // ~34KB, k-split partials (pad 17)
    __shared__ float sh1n[ROWS][HH];               // 8KB
    __shared__ float sGA[HH], sBA[HH], sGW[HH], sBW[HH];
    __shared__ float sStat[ROWS][4][2];
    __shared__ float scoord[ROWS][2];

    const int t    = threadIdx.x;
    const int j    = t & (HH - 1);     // H-column
    const int s    = t >> 8;           // k-half
    const int r0   = blockIdx.x * ROWS;
    const int warp = t >> 5;
    const int lane = t & 31;

    if (s == 0) {
        float wav = Wa[j], wwv = Ww[j];
        sGA[j] = gamma_a[j] * wav;  sBA[j] = beta_a[j] * wav;
        sGW[j] = gamma_w[j] * wwv;  sBW[j] = beta_w[j] * wwv;
    }
    const float bav = ba[0], bwv = bw[0];

    // Per-thread packed gate constants (pairs 01=(i,f), 23=(g,o)); used by s==0
    u64 bias0_01, bias0_23, bias1_01, bias1_23;
    u64 wi0a_01, wi0a_23, wi0b_01, wi0b_23;
    {
        float b0[4], b1[4], wa[4], wb[4];
#pragma unroll
        for (int g = 0; g < 4; g++) {
            int n = g * HH + j;
            b0[g] = bih0[n] + bhh0[n];
            b1[g] = bih1[n] + bhh1[n];
            wa[g] = Wih0[n * 2 + 0];
            wb[g] = Wih0[n * 2 + 1];
        }
        bias0_01 = pack2(b0[0], b0[1]); bias0_23 = pack2(b0[2], b0[3]);
        bias1_01 = pack2(b1[0], b1[1]); bias1_23 = pack2(b1[2], b1[3]);
        wi0a_01  = pack2(wa[0], wa[1]); wi0a_23  = pack2(wa[2], wa[3]);
        wi0b_01  = pack2(wb[0], wb[1]); wi0b_23  = pack2(wb[2], wb[3]);
    }

    // Stage noise (alias red as scratch)
    float* snoise = (float*)red;
    for (int i = t; i < ROWS * LAT; i += NT)
        snoise[i] = noise[(size_t)r0 * LAT + i];
    if (t < ROWS * 2) ((float*)scoord)[t] = 0.f;
    __syncthreads();

    // idea = elu(noise @ W_unpack^T + b_unpack); s==0 only (one-time)
    float c0r[ROWS], c1r[ROWS];
    if (s == 0) {
        float acc[ROWS];
        float bu = b_unpack[j];
#pragma unroll
        for (int r = 0; r < ROWS; r++) acc[r] = bu;
        for (int k = 0; k < LAT; k++) {
            float w = g_Wut[k * HH + j];
#pragma unroll
            for (int r = 0; r < ROWS; r++) acc[r] = fmaf(snoise[r * LAT + k], w, acc[r]);
        }
#pragma unroll
        for (int r = 0; r < ROWS; r++) {
            float v = acc[r];
            float e = (v > 0.f) ? v : (expf(v) - 1.f);
            sh0d[j][r] = pack2(e, e);
            c0r[r] = e;
            sh1d[j][r] = 0ull;
            sh1n[r][j] = 0.f;
            c1r[r] = 0.f;
        }
    }
    __syncthreads();

    // Weight pointers offset by this thread's k-half
    const float4* __restrict__ w0  = g_Wt0  + (size_t)(s * KHALF) * HH + j;
    const float4* __restrict__ w1i = g_Wt1i + (size_t)(s * KHALF) * HH + j;
    const float4* __restrict__ w1h = g_Wt1h + (size_t)(s * KHALF) * HH + j;
    const int kbase = s * KHALF;

    for (int step = 0; step < T; ++step) {
        // ================= layer 0 partials =================
        u64 a01[ROWS], a23[ROWS];
        if (s == 0) {
#pragma unroll
            for (int r = 0; r < ROWS; r++) {
                u64 cx = pack2(scoord[r][0], scoord[r][0]);
                u64 cy = pack2(scoord[r][1], scoord[r][1]);
                a01[r] = fma2(wi0a_01, cx, fma2(wi0b_01, cy, bias0_01));
                a23[r] = fma2(wi0a_23, cx, fma2(wi0b_23, cy, bias0_23));
            }
        } else {
#pragma unroll
            for (int r = 0; r < ROWS; r++) { a01[r] = 0ull; a23[r] = 0ull; }
        }
#pragma unroll 4
        for (int k = 0; k < KHALF; k++) {
            u64 w01, w23;
            ldg_v2u64(&w0[k * HH], w01, w23);
            const u64* hrow = sh0d[kbase + k];
            ulonglong2 h0 = *(const ulonglong2*)&hrow[0];
            ulonglong2 h1 = *(const ulonglong2*)&hrow[2];
            ulonglong2 h2 = *(const ulonglong2*)&hrow[4];
            ulonglong2 h3 = *(const ulonglong2*)&hrow[6];
            u64 h[ROWS] = {h0.x, h0.y, h1.x, h1.y, h2.x, h2.y, h3.x, h3.y};
#pragma unroll
            for (int r = 0; r < ROWS; r++) {
                a01[r] = fma2(w01, h[r], a01[r]);
                a23[r] = fma2(w23, h[r], a23[r]);
            }
        }
        if (s == 1) {
#pragma unroll
            for (int r = 0; r < ROWS; r++) {
                red[j][r]     = a01[r];
                red[j][8 + r] = a23[r];
            }
        }
        __syncthreads();                        // (A) partials ready, L0 reads done
        if (s == 0) {
            float h0new[ROWS];
#pragma unroll
            for (int r = 0; r < ROWS; r++) {
                float gi, gf, gg, go;
                unpack2(add2(a01[r], red[j][r]),     gi, gf);
                unpack2(add2(a23[r], red[j][8 + r]), gg, go);
                float cn = fmaf(sig_fast(gf), c0r[r], sig_fast(gi) * tanh_fast(gg));
                c0r[r]   = cn;
                h0new[r] = sig_fast(go) * tanh_fast(cn);
                sh0d[j][r] = pack2(h0new[r], h0new[r]);
            }
        }
        __syncthreads();                        // (B) new sh0d visible

        // ================= layer 1 partials =================
        if (s == 0) {
#pragma unroll
            for (int r = 0; r < ROWS; r++) { a01[r] = bias1_01; a23[r] = bias1_23; }
        } else {
#pragma unroll
            for (int r = 0; r < ROWS; r++) { a01[r] = 0ull; a23[r] = 0ull; }
        }
#pragma unroll 2
        for (int k = 0; k < KHALF; k++) {
            u64 wi01, wi23, wh01, wh23;
            ldg_v2u64(&w1i[k * HH], wi01, wi23);
            ldg_v2u64(&w1h[k * HH], wh01, wh23);
            const u64* prow = sh0d[kbase + k];
            const u64* qrow = sh1d[kbase + k];
            ulonglong2 p0 = *(const ulonglong2*)&prow[0];
            ulonglong2 p1 = *(const ulonglong2*)&prow[2];
            ulonglong2 p2 = *(const ulonglong2*)&prow[4];
            ulonglong2 p3 = *(const ulonglong2*)&prow[6];
            ulonglong2 q0 = *(const ulonglong2*)&qrow[0];
            ulonglong2 q1 = *(const ulonglong2*)&qrow[2];
            ulonglong2 q2 = *(const ulonglong2*)&qrow[4];
            ulonglong2 q3 = *(const ulonglong2*)&qrow[6];
            u64 ha[ROWS] = {p0.x, p0.y, p1.x, p1.y, p2.x, p2.y, p3.x, p3.y};
            u64 hb[ROWS] = {q0.x, q0.y, q1.x, q1.y, q2.x, q2.y, q3.x, q3.y};
#pragma unroll
            for (int r = 0; r < ROWS; r++) {
                a01[r] = fma2(wi01, ha[r], fma2(wh01, hb[r], a01[r]));
                a23[r] = fma2(wi23, ha[r], fma2(wh23, hb[r], a23[r]));
            }
        }
        if (s == 1) {
#pragma unroll
            for (int r = 0; r < ROWS; r++) {
                red[j][r]     = a01[r];
                red[j][8 + r] = a23[r];
            }
        }
        __syncthreads();                        // (C)
        if (s == 0) {
            float h1new[ROWS];
#pragma unroll
            for (int r = 0; r < ROWS; r++) {
                float gi, gf, gg, go;
                unpack2(add2(a01[r], red[j][r]),     gi, gf);
                unpack2(add2(a23[r], red[j][8 + r]), gg, go);
                float cn = fmaf(sig_fast(gf), c1r[r], sig_fast(gi) * tanh_fast(gg));
                c1r[r]   = cn;
                h1new[r] = sig_fast(go) * tanh_fast(cn);
                sh1d[j][r] = pack2(h1new[r], h1new[r]);
                sh1n[r][j] = h1new[r];
            }
        }
        __syncthreads();                        // (D) sh1n visible

        // ================= GroupNorm stats (warps 0-7 -> rows 0-7) =============
        if (warp < ROWS) {
            int r = warp;
#pragma unroll
            for (int g = 0; g < 4; g++) {
                float v0 = sh1n[r][g * GSIZE + lane];
                float v1 = sh1n[r][g * GSIZE + 32 + lane];
                float sm = v0 + v1, q = fmaf(v0, v0, v1 * v1);
#pragma unroll
                for (int off = 16; off; off >>= 1) {
                    sm += __shfl_xor_sync(0xffffffffu, sm, off);
                    q  += __shfl_xor_sync(0xffffffffu, q,  off);
                }
                if (lane == 0) {
                    float mu  = sm * (1.f / GSIZE);
                    float var = q * (1.f / GSIZE) - mu * mu;
                    sStat[r][g][0] = mu;
                    sStat[r][g][1] = rsqrtf(var + EPSG);
                }
            }
        }
        __syncthreads();                        // (E)

        // ================= heads =================
        if (warp < ROWS) {
            int r = warp;
            float aacc = 0.f, wacc = 0.f;
#pragma unroll
            for (int jj = 0; jj < HH; jj += 32) {
                int jx = jj + lane;
                int g  = jj >> 6;
                float xn = (sh1n[r][jx] - sStat[r][g][0]) * sStat[r][g][1];
                aacc += fmaf(xn, sGA[jx], sBA[jx]);
                wacc += fmaf(xn, sGW[jx], sBW[jx]);
            }
#pragma unroll
            for (int off = 16; off; off >>= 1) {
                aacc += __shfl_xor_sync(0xffffffffu, aacc, off);
                wacc += __shfl_xor_sync(0xffffffffu, wacc, off);
            }
            if (lane == 0) {
                float ang = tanh_fast(aacc + bav);
                float wid = sig_fast(wacc + bwv);
                scoord[r][0] = ang;
                scoord[r][1] = wid;
                float2* op = (float2*)(out + ((size_t)(r0 + r) * T + step) * 2);
                *op = make_float2(ang, wid);
            }
        }
        __syncthreads();                        // (F) scoord visible next step
    }
}

extern "C" void kernel_launch(void* const* d_in, const int* in_sizes, int n_in,
                              void* d_out, int out_size) {
    const float* noise    = (const float*)d_in[0];
    const float* W_unpack = (const float*)d_in[1];
    const float* b_unpack = (const float*)d_in[2];
    const float* Wih0     = (const float*)d_in[3];
    const float* Whh0     = (const float*)d_in[4];
    const float* bih0     = (const float*)d_in[5];
    const float* bhh0     = (const float*)d_in[6];
    const float* Wih1     = (const float*)d_in[7];
    const float* Whh1     = (const float*)d_in[8];
    const float* bih1     = (const float*)d_in[9];
    const float* bhh1     = (const float*)d_in[10];
    const float* gamma_a  = (const float*)d_in[11];
    const float* beta_a   = (const float*)d_in[12];
    const float* Wa       = (const float*)d_in[13];
    const float* ba       = (const float*)d_in[14];
    const float* gamma_w  = (const float*)d_in[15];
    const float* beta_w   = (const float*)d_in[16];
    const float* Ww       = (const float*)d_in[17];
    const float* bw       = (const float*)d_in[18];
    (void)in_sizes; (void)n_in;

    int T = out_size / (BB * 2);

    prep_kernel<<<(HH * FOURH + 255) / 256, 256>>>(Whh0, Wih1, Whh1, W_unpack);
    gen_kernel<<<NCTA, NT>>>(noise, b_unpack, Wih0, bih0, bhh0, bih1, bhh1,
                             gamma_a, beta_a, Wa, ba, gamma_w, beta_w, Ww, bw,
                             T, (float*)d_out);
}

// round 6
// speedup vs baseline: 1.6016x; 1.0462x over previous
#include <cuda_runtime.h>
#include <math.h>

#define BB     1024
#define HH     256
#define FOURH  1024
#define LAT    128
#define ROWS   7
#define NCTA   147              // 147*7 = 1029 >= 1024 (last CTA partially masked)
#define NT     512              // (j, s): j = t & 255 owns H-column, s = t >> 8 owns k-half
#define KHALF  128
#define GSIZE  64
#define EPSG   1e-5f

typedef unsigned long long u64;

// -------- device scratch --------
// Gate-interleaved, k-major transposed weights: [k][j] float4 = W[(g*H+j),k], g=i,f,g,o
__device__ float4 g_Wt0 [HH * HH];   // Whh0^T
__device__ float4 g_Wt1i[HH * HH];   // Wih1^T
__device__ float4 g_Wt1h[HH * HH];   // Whh1^T
__device__ float  g_Wut [LAT * HH];  // W_unpack^T [k][j]

__device__ __forceinline__ float tanh_fast(float x) {
    float y; asm("tanh.approx.f32 %0, %1;" : "=f"(y) : "f"(x)); return y;
}
__device__ __forceinline__ float sig_fast(float x) {
    return 0.5f * tanh_fast(0.5f * x) + 0.5f;
}
__device__ __forceinline__ u64 pack2(float lo, float hi) {
    u64 r; asm("mov.b64 %0, {%1, %2};" : "=l"(r) : "f"(lo), "f"(hi)); return r;
}
__device__ __forceinline__ void unpack2(u64 v, float& lo, float& hi) {
    asm("mov.b64 {%0, %1}, %2;" : "=f"(lo), "=f"(hi) : "l"(v));
}
__device__ __forceinline__ u64 fma2(u64 a, u64 b, u64 c) {
    u64 d; asm("fma.rn.f32x2 %0, %1, %2, %3;" : "=l"(d) : "l"(a), "l"(b), "l"(c)); return d;
}
__device__ __forceinline__ u64 add2(u64 a, u64 b) {
    u64 d; asm("add.rn.f32x2 %0, %1, %2;" : "=l"(d) : "l"(a), "l"(b)); return d;
}
__device__ __forceinline__ void ldg_v2u64(const void* p, u64& a, u64& b) {
    asm("ld.global.nc.v2.u64 {%0, %1}, [%2];" : "=l"(a), "=l"(b) : "l"(p));
}

// -------- prologue: transpose weights --------
__global__ void prep_kernel(const float* __restrict__ Whh0,
                            const float* __restrict__ Wih1,
                            const float* __restrict__ Whh1,
                            const float* __restrict__ Wu) {
    int i = blockIdx.x * blockDim.x + threadIdx.x;
    if (i < HH * FOURH) {
        int k   = i >> 10;
        int rem = i & 1023;
        int j   = rem >> 2;
        int g   = rem & 3;
        int src = (g * HH + j) * HH + k;
        ((float*)g_Wt0)[i]  = Whh0[src];
        ((float*)g_Wt1i)[i] = Wih1[src];
        ((float*)g_Wt1h)[i] = Whh1[src];
    }
    if (i < LAT * HH) {
        int k = i >> 8, j = i & 255;
        g_Wut[i] = Wu[j * LAT + k];
    }
}

// -------- main persistent kernel --------
__global__ __launch_bounds__(NT, 1)
void gen_kernel(const float* __restrict__ noise,
                const float* __restrict__ b_unpack,
                const float* __restrict__ Wih0,
                const float* __restrict__ bih0, const float* __restrict__ bhh0,
                const float* __restrict__ bih1, const float* __restrict__ bhh1,
                const float* __restrict__ gamma_a, const float* __restrict__ beta_a,
                const float* __restrict__ Wa, const float* __restrict__ ba,
                const float* __restrict__ gamma_w, const float* __restrict__ beta_w,
                const float* __restrict__ Ww, const float* __restrict__ bw,
                int T, float* __restrict__ out) {
    // h duplicated per element as (h,h) u64: [k][r] (row dim padded to 8)
    __shared__ __align__(16) u64 sh0d[HH][8];      // 16KB
    __shared__ __align__(16) u64 sh1d[HH][8];      // 16KB
    __shared__ __align__(16) u64 red[HH][17];      // ~34KB, k-split partials
    __shared__ float sh1n[ROWS][HH];               // 7KB
    __shared__ float sGA[HH], sBA[HH], sGW[HH], sBW[HH];
    __shared__ float sStat[ROWS][4][2];
    __shared__ float scoord[ROWS][2];

    const int t    = threadIdx.x;
    const int j    = t & (HH - 1);     // H-column
    const int s    = t >> 8;           // k-half
    const int r0   = blockIdx.x * ROWS;
    const int warp = t >> 5;
    const int lane = t & 31;

    if (s == 0) {
        float wav = Wa[j], wwv = Ww[j];
        sGA[j] = gamma_a[j] * wav;  sBA[j] = beta_a[j] * wav;
        sGW[j] = gamma_w[j] * wwv;  sBW[j] = beta_w[j] * wwv;
    }
    const float bav = ba[0], bwv = bw[0];

    // Per-thread packed gate constants (pairs 01=(i,f), 23=(g,o)); used by s==0
    u64 bias0_01, bias0_23, bias1_01, bias1_23;
    u64 wi0a_01, wi0a_23, wi0b_01, wi0b_23;
    {
        float b0[4], b1[4], wa[4], wb[4];
#pragma unroll
        for (int g = 0; g < 4; g++) {
            int n = g * HH + j;
            b0[g] = bih0[n] + bhh0[n];
            b1[g] = bih1[n] + bhh1[n];
            wa[g] = Wih0[n * 2 + 0];
            wb[g] = Wih0[n * 2 + 1];
        }
        bias0_01 = pack2(b0[0], b0[1]); bias0_23 = pack2(b0[2], b0[3]);
        bias1_01 = pack2(b1[0], b1[1]); bias1_23 = pack2(b1[2], b1[3]);
        wi0a_01  = pack2(wa[0], wa[1]); wi0a_23  = pack2(wa[2], wa[3]);
        wi0b_01  = pack2(wb[0], wb[1]); wi0b_23  = pack2(wb[2], wb[3]);
    }

    // Stage noise (alias red as scratch); clamp row index for padding rows
    float* snoise = (float*)red;
    for (int i = t; i < ROWS * LAT; i += NT) {
        int rr = i / LAT, kk = i - rr * LAT;
        int src_row = min(r0 + rr, BB - 1);
        snoise[i] = noise[(size_t)src_row * LAT + kk];
    }
    if (t < ROWS * 2) ((float*)scoord)[t] = 0.f;
    __syncthreads();

    // idea = elu(noise @ W_unpack^T + b_unpack); s==0 only (one-time)
    float c0r[ROWS], c1r[ROWS];
    if (s == 0) {
        float acc[ROWS];
        float bu = b_unpack[j];
#pragma unroll
        for (int r = 0; r < ROWS; r++) acc[r] = bu;
        for (int k = 0; k < LAT; k++) {
            float w = g_Wut[k * HH + j];
#pragma unroll
            for (int r = 0; r < ROWS; r++) acc[r] = fmaf(snoise[r * LAT + k], w, acc[r]);
        }
#pragma unroll
        for (int r = 0; r < ROWS; r++) {
            float v = acc[r];
            float e = (v > 0.f) ? v : (expf(v) - 1.f);
            sh0d[j][r] = pack2(e, e);
            c0r[r] = e;
            sh1d[j][r] = 0ull;
            sh1n[r][j] = 0.f;
            c1r[r] = 0.f;
        }
        // pad row 7 so vector LDS of rows 6-7 reads defined data
        sh0d[j][7] = 0ull;
        sh1d[j][7] = 0ull;
    }
    __syncthreads();

    // Weight pointers offset by this thread's k-half
    const float4* __restrict__ w0  = g_Wt0  + (size_t)(s * KHALF) * HH + j;
    const float4* __restrict__ w1i = g_Wt1i + (size_t)(s * KHALF) * HH + j;
    const float4* __restrict__ w1h = g_Wt1h + (size_t)(s * KHALF) * HH + j;
    const int kbase = s * KHALF;

    for (int step = 0; step < T; ++step) {
        // ================= layer 0 partials =================
        u64 a01[ROWS], a23[ROWS];
        if (s == 0) {
#pragma unroll
            for (int r = 0; r < ROWS; r++) {
                u64 cx = pack2(scoord[r][0], scoord[r][0]);
                u64 cy = pack2(scoord[r][1], scoord[r][1]);
                a01[r] = fma2(wi0a_01, cx, fma2(wi0b_01, cy, bias0_01));
                a23[r] = fma2(wi0a_23, cx, fma2(wi0b_23, cy, bias0_23));
            }
        } else {
#pragma unroll
            for (int r = 0; r < ROWS; r++) { a01[r] = 0ull; a23[r] = 0ull; }
        }
#pragma unroll 8
        for (int k = 0; k < KHALF; k++) {
            u64 w01, w23;
            ldg_v2u64(&w0[k * HH], w01, w23);
            const u64* hrow = sh0d[kbase + k];
            ulonglong2 h0 = *(const ulonglong2*)&hrow[0];
            ulonglong2 h1 = *(const ulonglong2*)&hrow[2];
            ulonglong2 h2 = *(const ulonglong2*)&hrow[4];
            u64 h6 = hrow[6];
            u64 h[ROWS] = {h0.x, h0.y, h1.x, h1.y, h2.x, h2.y, h6};
#pragma unroll
            for (int r = 0; r < ROWS; r++) {
                a01[r] = fma2(w01, h[r], a01[r]);
                a23[r] = fma2(w23, h[r], a23[r]);
            }
        }
        if (s == 1) {
#pragma unroll
            for (int r = 0; r < ROWS; r++) {
                red[j][r]     = a01[r];
                red[j][8 + r] = a23[r];
            }
        }
        __syncthreads();                        // (A) partials ready, L0 reads done
        if (s == 0) {
#pragma unroll
            for (int r = 0; r < ROWS; r++) {
                float gi, gf, gg, go;
                unpack2(add2(a01[r], red[j][r]),     gi, gf);
                unpack2(add2(a23[r], red[j][8 + r]), gg, go);
                float cn = fmaf(sig_fast(gf), c0r[r], sig_fast(gi) * tanh_fast(gg));
                c0r[r]   = cn;
                float hn = sig_fast(go) * tanh_fast(cn);
                sh0d[j][r] = pack2(hn, hn);
            }
        }
        __syncthreads();                        // (B) new sh0d visible

        // ================= layer 1 partials =================
        if (s == 0) {
#pragma unroll
            for (int r = 0; r < ROWS; r++) { a01[r] = bias1_01; a23[r] = bias1_23; }
        } else {
#pragma unroll
            for (int r = 0; r < ROWS; r++) { a01[r] = 0ull; a23[r] = 0ull; }
        }
#pragma unroll 4
        for (int k = 0; k < KHALF; k++) {
            u64 wi01, wi23, wh01, wh23;
            ldg_v2u64(&w1i[k * HH], wi01, wi23);
            ldg_v2u64(&w1h[k * HH], wh01, wh23);
            const u64* prow = sh0d[kbase + k];
            const u64* qrow = sh1d[kbase + k];
            ulonglong2 p0 = *(const ulonglong2*)&prow[0];
            ulonglong2 p1 = *(const ulonglong2*)&prow[2];
            ulonglong2 p2 = *(const ulonglong2*)&prow[4];
            u64 p6 = prow[6];
            ulonglong2 q0 = *(const ulonglong2*)&qrow[0];
            ulonglong2 q1 = *(const ulonglong2*)&qrow[2];
            ulonglong2 q2 = *(const ulonglong2*)&qrow[4];
            u64 q6 = qrow[6];
            u64 ha[ROWS] = {p0.x, p0.y, p1.x, p1.y, p2.x, p2.y, p6};
            u64 hb[ROWS] = {q0.x, q0.y, q1.x, q1.y, q2.x, q2.y, q6};
#pragma unroll
            for (int r = 0; r < ROWS; r++) {
                a01[r] = fma2(wi01, ha[r], fma2(wh01, hb[r], a01[r]));
                a23[r] = fma2(wi23, ha[r], fma2(wh23, hb[r], a23[r]));
            }
        }
        if (s == 1) {
#pragma unroll
            for (int r = 0; r < ROWS; r++) {
                red[j][r]     = a01[r];
                red[j][8 + r] = a23[r];
            }
        }
        __syncthreads();                        // (C)
        if (s == 0) {
#pragma unroll
            for (int r = 0; r < ROWS; r++) {
                float gi, gf, gg, go;
                unpack2(add2(a01[r], red[j][r]),     gi, gf);
                unpack2(add2(a23[r], red[j][8 + r]), gg, go);
                float cn = fmaf(sig_fast(gf), c1r[r], sig_fast(gi) * tanh_fast(gg));
                c1r[r]   = cn;
                float hn = sig_fast(go) * tanh_fast(cn);
                sh1d[j][r] = pack2(hn, hn);
                sh1n[r][j] = hn;
            }
        }
        __syncthreads();                        // (D) sh1n visible

        // ================= GroupNorm stats (warps 0-6 -> rows 0-6) =============
        if (warp < ROWS) {
            int r = warp;
#pragma unroll
            for (int g = 0; g < 4; g++) {
                float v0 = sh1n[r][g * GSIZE + lane];
                float v1 = sh1n[r][g * GSIZE + 32 + lane];
                float sm = v0 + v1, q = fmaf(v0, v0, v1 * v1);
#pragma unroll
                for (int off = 16; off; off >>= 1) {
                    sm += __shfl_xor_sync(0xffffffffu, sm, off);
                    q  += __shfl_xor_sync(0xffffffffu, q,  off);
                }
                if (lane == 0) {
                    float mu  = sm * (1.f / GSIZE);
                    float var = q * (1.f / GSIZE) - mu * mu;
                    sStat[r][g][0] = mu;
                    sStat[r][g][1] = rsqrtf(var + EPSG);
                }
            }
        }
        __syncthreads();                        // (E)

        // ================= heads =================
        if (warp < ROWS) {
            int r = warp;
            float aacc = 0.f, wacc = 0.f;
#pragma unroll
            for (int jj = 0; jj < HH; jj += 32) {
                int jx = jj + lane;
                int g  = jj >> 6;
                float xn = (sh1n[r][jx] - sStat[r][g][0]) * sStat[r][g][1];
                aacc += fmaf(xn, sGA[jx], sBA[jx]);
                wacc += fmaf(xn, sGW[jx], sBW[jx]);
            }
#pragma unroll
            for (int off = 16; off; off >>= 1) {
                aacc += __shfl_xor_sync(0xffffffffu, aacc, off);
                wacc += __shfl_xor_sync(0xffffffffu, wacc, off);
            }
            if (lane == 0) {
                float ang = tanh_fast(aacc + bav);
                float wid = sig_fast(wacc + bwv);
                scoord[r][0] = ang;
                scoord[r][1] = wid;
                if (r0 + r < BB) {
                    float2* op = (float2*)(out + ((size_t)(r0 + r) * T + step) * 2);
                    *op = make_float2(ang, wid);
                }
            }
        }
        __syncthreads();                        // (F) scoord visible next step
    }
}

extern "C" void kernel_launch(void* const* d_in, const int* in_sizes, int n_in,
                              void* d_out, int out_size) {
    const float* noise    = (const float*)d_in[0];
    const float* W_unpack = (const float*)d_in[1];
    const float* b_unpack = (const float*)d_in[2];
    const float* Wih0     = (const float*)d_in[3];
    const float* Whh0     = (const float*)d_in[4];
    const float* bih0     = (const float*)d_in[5];
    const float* bhh0     = (const float*)d_in[6];
    const float* Wih1     = (const float*)d_in[7];
    const float* Whh1     = (const float*)d_in[8];
    const float* bih1     = (const float*)d_in[9];
    const float* bhh1     = (const float*)d_in[10];
    const float* gamma_a  = (const float*)d_in[11];
    const float* beta_a   = (const float*)d_in[12];
    const float* Wa       = (const float*)d_in[13];
    const float* ba       = (const float*)d_in[14];
    const float* gamma_w  = (const float*)d_in[15];
    const float* beta_w   = (const float*)d_in[16];
    const float* Ww       = (const float*)d_in[17];
    const float* bw       = (const float*)d_in[18];
    (void)in_sizes; (void)n_in;

    int T = out_size / (BB * 2);

    prep_kernel<<<(HH * FOURH + 255) / 256, 256>>>(Whh0, Wih1, Whh1, W_unpack);
    gen_kernel<<<NCTA, NT>>>(noise, b_unpack, Wih0, bih0, bhh0, bih1, bhh1,
                             gamma_a, beta_a, Wa, ba, gamma_w, beta_w, Ww, bw,
                             T, (float*)d_out);
}